// round 15
// baseline (speedup 1.0000x reference)
#include <cuda_runtime.h>
#include <cuda_bf16.h>

#define BATCH 2
#define SEQ   2048
#define HID   2048
#define NHEAD 16
#define DK    128
#define MROWS (BATCH*SEQ)

// ---------------- scratch (allocation-free) ----------------
__device__ __nv_bfloat16 g_x_hi[(size_t)MROWS * HID];
__device__ __nv_bfloat16 g_x_lo[(size_t)MROWS * HID];
__device__ __nv_bfloat16 g_w_hi[4][(size_t)HID * HID];
__device__ __nv_bfloat16 g_w_lo[4][(size_t)HID * HID];
__device__ __nv_bfloat16 g_q_hi[(size_t)MROWS * HID];
__device__ __nv_bfloat16 g_q_lo[(size_t)MROWS * HID];
__device__ __nv_bfloat16 g_k_hi[(size_t)MROWS * HID];
__device__ __nv_bfloat16 g_k_lo[(size_t)MROWS * HID];
__device__ __nv_bfloat16 g_v_hi[(size_t)MROWS * HID];
__device__ __nv_bfloat16 g_v_lo[(size_t)MROWS * HID];
__device__ __nv_bfloat16 g_ao_hi[(size_t)MROWS * HID];
__device__ __nv_bfloat16 g_ao_lo[(size_t)MROWS * HID];

// ---------------- PTX helpers (sm_80-era, nothing 'a'-gated) ----------------
__device__ __forceinline__ unsigned smem_u32(const void* p) {
    unsigned a;
    asm("{ .reg .u64 t; cvta.to.shared.u64 t, %1; cvt.u32.u64 %0, t; }" : "=r"(a) : "l"(p));
    return a;
}
__device__ __forceinline__ void cp16(unsigned s, const void* g) {
    asm volatile("cp.async.cg.shared.global [%0], [%1], 16;" :: "r"(s), "l"(g));
}
#define CP_COMMIT() asm volatile("cp.async.commit_group;" ::: "memory")
#define CP_WAIT(n)  asm volatile("cp.async.wait_group %0;" :: "n"(n) : "memory")

__device__ __forceinline__ void ldm4(unsigned* r, unsigned addr) {
    asm volatile("ldmatrix.sync.aligned.m8n8.x4.shared.b16 {%0,%1,%2,%3}, [%4];"
        : "=r"(r[0]), "=r"(r[1]), "=r"(r[2]), "=r"(r[3]) : "r"(addr));
}
__device__ __forceinline__ void ldm4t(unsigned* r, unsigned addr) {
    asm volatile("ldmatrix.sync.aligned.m8n8.x4.trans.shared.b16 {%0,%1,%2,%3}, [%4];"
        : "=r"(r[0]), "=r"(r[1]), "=r"(r[2]), "=r"(r[3]) : "r"(addr));
}
__device__ __forceinline__ void mma_bf16(float* d, const unsigned* a, const unsigned* b) {
    asm volatile(
        "mma.sync.aligned.m16n8k16.row.col.f32.bf16.bf16.f32 "
        "{%0,%1,%2,%3}, {%4,%5,%6,%7}, {%8,%9}, {%0,%1,%2,%3};"
        : "+f"(d[0]), "+f"(d[1]), "+f"(d[2]), "+f"(d[3])
        : "r"(a[0]), "r"(a[1]), "r"(a[2]), "r"(a[3]), "r"(b[0]), "r"(b[1]));
}

__device__ __forceinline__ __nv_bfloat162 split_pair(float a0, float a1,
                                                     __nv_bfloat162* lo_out) {
    __nv_bfloat16 h0 = __float2bfloat16(a0);
    __nv_bfloat16 h1 = __float2bfloat16(a1);
    *lo_out = __nv_bfloat162(__float2bfloat16(a0 - __bfloat162float(h0)),
                             __float2bfloat16(a1 - __bfloat162float(h1)));
    return __nv_bfloat162(h0, h1);
}

// ---------------- fused fp32 -> bf16 hi/lo split (ONE launch) ----------------
#define X4   ((MROWS * HID) / 4)
#define W4   ((HID * HID) / 4)
#define TOT4 (X4 + 4 * W4)

__global__ __launch_bounds__(256)
void split_all(const float* __restrict__ x,
               const float* __restrict__ w0, const float* __restrict__ w1,
               const float* __restrict__ w2, const float* __restrict__ w3,
               __nv_bfloat16* __restrict__ xhi, __nv_bfloat16* __restrict__ xlo,
               __nv_bfloat16* __restrict__ whi, __nv_bfloat16* __restrict__ wlo)
{
    int i = blockIdx.x * 256 + threadIdx.x;
    if (i >= TOT4) return;
    const float* src;
    __nv_bfloat16 *hi, *lo;
    int idx;
    if (i < X4) {
        src = x; hi = xhi; lo = xlo; idx = i;
    } else {
        int j = i - X4;
        int wi = j / W4;
        idx = j - wi * W4;
        const float* ws[4] = {w0, w1, w2, w3};
        src = ws[wi];
        hi = whi + (size_t)wi * HID * HID;
        lo = wlo + (size_t)wi * HID * HID;
    }
    float4 v = ((const float4*)src)[idx];
    __nv_bfloat162 l0, l1;
    __nv_bfloat162 h0 = split_pair(v.x, v.y, &l0);
    __nv_bfloat162 h1 = split_pair(v.z, v.w, &l1);
    ((__nv_bfloat162*)hi)[2*idx+0] = h0;
    ((__nv_bfloat162*)hi)[2*idx+1] = h1;
    ((__nv_bfloat162*)lo)[2*idx+0] = l0;
    ((__nv_bfloat162*)lo)[2*idx+1] = l1;
}

// ---------------- mma.sync GEMM: 3-stage cp.async pipeline ----------------
// 128x128 tile, BK=32, 8 warps (2m x 4n). Smem: 144B pitch rows, hi at +0,
// lo at +64 per row. ldmatrix issues INTERLEAVED with MMA batches so the
// smem crossbar runs concurrently with the tensor pipe instead of in a
// serial per-iteration phase.
#define BKI   32
#define PITCH 144
#define A_BLK (128 * PITCH)           // 18432
#define STAGE (2 * A_BLK)             // 36864
#define GEMM_SMEM (3 * STAGE)         // 110592
#define NKIT (HID / BKI)              // 64

__device__ __forceinline__ void gemm_load_stage(
    const __nv_bfloat16* __restrict__ Ahi, const __nv_bfloat16* __restrict__ Alo,
    const __nv_bfloat16* __restrict__ Bhi, const __nv_bfloat16* __restrict__ Blo,
    int rowBase, int colBase, int k0, unsigned stage, int t)
{
    const int r    = t >> 1;
    const int half = t & 1;
    const size_t ga = (size_t)(rowBase + r) * HID + k0 + half * 16;
    const size_t gb = (size_t)(colBase + r) * HID + k0 + half * 16;
    const unsigned sa = stage + r * PITCH + half * 32;
    const unsigned sb = sa + A_BLK;
    cp16(sa,          Ahi + ga);
    cp16(sa + 16,     Ahi + ga + 8);
    cp16(sa + 64,     Alo + ga);
    cp16(sa + 80,     Alo + ga + 8);
    cp16(sb,          Bhi + gb);
    cp16(sb + 16,     Bhi + gb + 8);
    cp16(sb + 64,     Blo + gb);
    cp16(sb + 80,     Blo + gb + 8);
}

#define MMA_ROW(accv, afrag, b0, b1)                                   \
    mma_bf16(accv[0], afrag, &b0[0]); mma_bf16(accv[1], afrag, &b0[2]); \
    mma_bf16(accv[2], afrag, &b1[0]); mma_bf16(accv[3], afrag, &b1[2]);

// If Cf != nullptr: write fp32. Else write bf16 hi/lo split to Chi/Clo.
__device__ __forceinline__ void gemm_body(
    const __nv_bfloat16* __restrict__ Ahi, const __nv_bfloat16* __restrict__ Alo,
    const __nv_bfloat16* __restrict__ Bhi, const __nv_bfloat16* __restrict__ Blo,
    float* __restrict__ Cf,
    __nv_bfloat16* __restrict__ Chi, __nv_bfloat16* __restrict__ Clo,
    const float* __restrict__ freqs, int do_rope)
{
    extern __shared__ char sm[];
    const unsigned smem = smem_u32(sm);
    const int t    = threadIdx.x;
    const int wid  = t >> 5;
    const int lane = t & 31;
    const int wm   = wid & 1;
    const int wn   = wid >> 1;
    const int rowBase = blockIdx.y * 128;
    const int colBase = blockIdx.x * 128;

    const unsigned aOff = (wm * 64 + (lane & 15)) * PITCH + ((lane >> 4) & 1) * 16;
    const unsigned bOff = A_BLK + (wn * 32 + ((lane >> 4) & 1) * 8 + (lane & 7)) * PITCH
                        + ((lane >> 3) & 1) * 16;

    float acc[4][4][4];
    #pragma unroll
    for (int mt = 0; mt < 4; ++mt)
        #pragma unroll
        for (int nt = 0; nt < 4; ++nt)
            #pragma unroll
            for (int c = 0; c < 4; ++c) acc[mt][nt][c] = 0.f;

    gemm_load_stage(Ahi, Alo, Bhi, Blo, rowBase, colBase, 0,   smem,         t);
    CP_COMMIT();
    gemm_load_stage(Ahi, Alo, Bhi, Blo, rowBase, colBase, BKI, smem + STAGE, t);
    CP_COMMIT();

    int s_cur = 0, s_pf = 2;
    for (int it = 0; it < NKIT; ++it) {
        CP_WAIT(1);
        __syncthreads();

        if (it + 2 < NKIT)
            gemm_load_stage(Ahi, Alo, Bhi, Blo, rowBase, colBase, (it + 2) * BKI,
                            smem + s_pf * STAGE, t);
        CP_COMMIT();

        const unsigned cur = smem + s_cur * STAGE;
        #pragma unroll
        for (int ks = 0; ks < 2; ++ks) {
            const unsigned kofs = ks * 32;
            const unsigned aB = cur + aOff + kofs;      // hi A base
            const unsigned bB = cur + bOff + kofs;      // hi B base
            unsigned ah[4][4], al[4][4], bh[2][4], bl[2][4];

            // phase 0: load A-hi + B-hi
            ldm4(ah[0], aB);
            ldm4(ah[1], aB + 16 * PITCH);
            ldm4(ah[2], aB + 32 * PITCH);
            ldm4(ah[3], aB + 48 * PITCH);
            ldm4(bh[0], bB);
            ldm4(bh[1], bB + 16 * PITCH);

            // hh mt=0,1 while loading A-lo first half
            MMA_ROW(acc[0], ah[0], bh[0], bh[1]);
            ldm4(al[0], aB + 64);
            MMA_ROW(acc[1], ah[1], bh[0], bh[1]);
            ldm4(al[1], aB + 16 * PITCH + 64);

            // hh mt=2,3 while loading A-lo second half
            MMA_ROW(acc[2], ah[2], bh[0], bh[1]);
            ldm4(al[2], aB + 32 * PITCH + 64);
            MMA_ROW(acc[3], ah[3], bh[0], bh[1]);
            ldm4(al[3], aB + 48 * PITCH + 64);

            // lh mt=0,1 while loading B-lo
            MMA_ROW(acc[0], al[0], bh[0], bh[1]);
            ldm4(bl[0], bB + 64);
            MMA_ROW(acc[1], al[1], bh[0], bh[1]);
            ldm4(bl[1], bB + 16 * PITCH + 64);

            // lh mt=2,3
            MMA_ROW(acc[2], al[2], bh[0], bh[1]);
            MMA_ROW(acc[3], al[3], bh[0], bh[1]);

            // hl all
            MMA_ROW(acc[0], ah[0], bl[0], bl[1]);
            MMA_ROW(acc[1], ah[1], bl[0], bl[1]);
            MMA_ROW(acc[2], ah[2], bl[0], bl[1]);
            MMA_ROW(acc[3], ah[3], bl[0], bl[1]);
        }

        s_cur = (s_cur == 2) ? 0 : s_cur + 1;
        s_pf  = (s_pf  == 2) ? 0 : s_pf  + 1;
    }

    const int g   = lane >> 2;
    const int tig = lane & 3;
    #pragma unroll
    for (int mt = 0; mt < 4; ++mt) {
        #pragma unroll
        for (int nt = 0; nt < 4; ++nt) {
            const int m0 = rowBase + wm * 64 + mt * 16 + g;
            const int n0 = colBase + wn * 32 + nt * 8 + tig * 2;
            float v0 = acc[mt][nt][0], v1 = acc[mt][nt][1];
            float v2 = acc[mt][nt][2], v3 = acc[mt][nt][3];
            if (do_rope) {
                const int d = n0 & (DK - 1);
                const int s0 = m0 & (SEQ - 1);
                const int s1 = (m0 + 8) & (SEQ - 1);
                const float cs0 = freqs[s0 * DK + d], sn0 = freqs[s0 * DK + d + 1];
                const float cs1 = freqs[s1 * DK + d], sn1 = freqs[s1 * DK + d + 1];
                float r0 = v0 * cs0 - v1 * sn0, r1 = v0 * sn0 + v1 * cs0;
                float r2 = v2 * cs1 - v3 * sn1, r3 = v2 * sn1 + v3 * cs1;
                v0 = r0; v1 = r1; v2 = r2; v3 = r3;
            }
            if (Cf) {
                *(float2*)(Cf + (size_t)m0 * HID + n0)       = make_float2(v0, v1);
                *(float2*)(Cf + (size_t)(m0 + 8) * HID + n0) = make_float2(v2, v3);
            } else {
                __nv_bfloat162 l0, l1;
                __nv_bfloat162 h0 = split_pair(v0, v1, &l0);
                __nv_bfloat162 h1 = split_pair(v2, v3, &l1);
                *(__nv_bfloat162*)(Chi + (size_t)m0 * HID + n0)       = h0;
                *(__nv_bfloat162*)(Chi + (size_t)(m0 + 8) * HID + n0) = h1;
                *(__nv_bfloat162*)(Clo + (size_t)m0 * HID + n0)       = l0;
                *(__nv_bfloat162*)(Clo + (size_t)(m0 + 8) * HID + n0) = l1;
            }
        }
    }
}

__global__ __launch_bounds__(256, 2)
void gemm_qkv(const __nv_bfloat16* __restrict__ xhi, const __nv_bfloat16* __restrict__ xlo,
              const __nv_bfloat16* __restrict__ whi, const __nv_bfloat16* __restrict__ wlo,
              __nv_bfloat16* __restrict__ qhi, __nv_bfloat16* __restrict__ qlo,
              __nv_bfloat16* __restrict__ khi, __nv_bfloat16* __restrict__ klo,
              __nv_bfloat16* __restrict__ vhi, __nv_bfloat16* __restrict__ vlo,
              const float* __restrict__ freqs)
{
    const int z = blockIdx.z;
    const __nv_bfloat16* bh = whi + (size_t)z * HID * HID;
    const __nv_bfloat16* bl = wlo + (size_t)z * HID * HID;
    __nv_bfloat16* Chi = (z == 0) ? qhi : ((z == 1) ? khi : vhi);
    __nv_bfloat16* Clo = (z == 0) ? qlo : ((z == 1) ? klo : vlo);
    gemm_body(xhi, xlo, bh, bl, nullptr, Chi, Clo, freqs, z < 2 ? 1 : 0);
}

__global__ __launch_bounds__(256, 2)
void gemm_single(const __nv_bfloat16* __restrict__ ahi, const __nv_bfloat16* __restrict__ alo,
                 const __nv_bfloat16* __restrict__ bhi, const __nv_bfloat16* __restrict__ blo,
                 float* __restrict__ C)
{
    gemm_body(ahi, alo, bhi, blo, C, nullptr, nullptr, nullptr, 0);
}

// ---------------------------------------------------------------------------
// Tensorized flash attention (bf16 hi/lo, 3-product), fp32 softmax/O state.
// (unchanged — measured at its HMMA floor)
// ---------------------------------------------------------------------------
#define KT2    32
#define QP     272
#define PP     80
#define SQ_HI  0
#define SQ_LO  (SQ_HI + 64 * QP)
#define SK_HI  (SQ_LO + 64 * QP)
#define SK_LO  (SK_HI + 32 * QP)
#define SV_HI  (SK_LO + 32 * QP)
#define SV_LO  (SV_HI + 32 * QP)
#define SP_HI  (SV_LO + 32 * QP)
#define SP_LO  (SP_HI + 64 * PP)
#define RED_MX (SP_LO + 64 * PP)
#define RED_SM (RED_MX + 2 * 64 * 4)
#define ATTN_SMEM (RED_SM + 2 * 64 * 4)

__global__ __launch_bounds__(256, 2)
void attn_mma(const __nv_bfloat16* __restrict__ qhi, const __nv_bfloat16* __restrict__ qlo,
              const __nv_bfloat16* __restrict__ khi, const __nv_bfloat16* __restrict__ klo,
              const __nv_bfloat16* __restrict__ vhi, const __nv_bfloat16* __restrict__ vlo,
              __nv_bfloat16* __restrict__ ohi, __nv_bfloat16* __restrict__ olo)
{
    extern __shared__ char sm[];
    const unsigned smem = smem_u32(sm);
    float* redmx = (float*)(sm + RED_MX);
    float* redsm = (float*)(sm + RED_SM);

    const int t    = threadIdx.x;
    const int wid  = t >> 5;
    const int lane = t & 31;
    const int wm   = wid & 3;
    const int wn   = wid >> 2;
    const int g    = lane >> 2;
    const int tig  = lane & 3;

    const int qt = gridDim.x - 1 - blockIdx.x;
    const int b  = blockIdx.y >> 4;
    const int h  = blockIdx.y & 15;
    const int q0 = qt * 64;
    const size_t headoff = (size_t)b * SEQ * HID + (size_t)h * DK;

    const unsigned aQ = (wm * 16 + (lane & 15)) * QP + ((lane >> 4) & 1) * 16;
    const unsigned bK = (wn * 16 + ((lane >> 4) & 1) * 8 + (lane & 7)) * QP
                      + ((lane >> 3) & 1) * 16;
    const unsigned aP = (wm * 16 + (lane & 15)) * PP + ((lane >> 4) & 1) * 16;
    const unsigned bVt = ((lane & 7) + ((lane >> 3) & 1) * 8) * QP
                       + ((lane >> 4) & 1) * 16 + wn * 128;

    {
        const int c = t & 15;
        #pragma unroll
        for (int pass = 0; pass < 4; ++pass) {
            const int r = (t >> 4) + pass * 16;
            const size_t gq = headoff + (size_t)(q0 + r) * HID + c * 8;
            cp16(smem + SQ_HI + r * QP + c * 16, qhi + gq);
            cp16(smem + SQ_LO + r * QP + c * 16, qlo + gq);
        }
    }
    CP_COMMIT();

    float o[8][4];
    #pragma unroll
    for (int nt = 0; nt < 8; ++nt)
        #pragma unroll
        for (int c = 0; c < 4; ++c) o[nt][c] = 0.f;
    float m_i[2] = {-1e30f, -1e30f};
    float l_i[2] = {0.f, 0.f};
    const float scale = 0.088388347648318447f;

    const int njt = 2 * (qt + 1);
    for (int j = 0; j < njt; ++j) {
        const int kbase = j * KT2;
        __syncthreads();

        {
            const int c = t & 15;
            #pragma unroll
            for (int pass = 0; pass < 2; ++pass) {
                const int r = (t >> 4) + pass * 16;
                const size_t gk = headoff + (size_t)(kbase + r) * HID + c * 8;
                cp16(smem + SK_HI + r * QP + c * 16, khi + gk);
                cp16(smem + SK_LO + r * QP + c * 16, klo + gk);
                cp16(smem + SV_HI + r * QP + c * 16, vhi + gk);
                cp16(smem + SV_LO + r * QP + c * 16, vlo + gk);
            }
        }
        CP_COMMIT();
        CP_WAIT(0);
        __syncthreads();

        float s[2][4];
        #pragma unroll
        for (int nt = 0; nt < 2; ++nt)
            #pragma unroll
            for (int c = 0; c < 4; ++c) s[nt][c] = 0.f;

        #pragma unroll
        for (int ks = 0; ks < 8; ++ks) {
            const unsigned ko = ks * 32;
            unsigned qh[4], ql[4], kh[4], kl[4];
            ldm4(qh, smem + SQ_HI + aQ + ko);
            ldm4(ql, smem + SQ_LO + aQ + ko);
            ldm4(kh, smem + SK_HI + bK + ko);
            ldm4(kl, smem + SK_LO + bK + ko);
            #pragma unroll
            for (int nt = 0; nt < 2; ++nt)
                mma_bf16(s[nt], qh, &kh[nt * 2]);
            #pragma unroll
            for (int nt = 0; nt < 2; ++nt)
                mma_bf16(s[nt], qh, &kl[nt * 2]);
            #pragma unroll
            for (int nt = 0; nt < 2; ++nt)
                mma_bf16(s[nt], ql, &kh[nt * 2]);
        }

        const bool maskt = (kbase + KT2 - 1 > q0 + wm * 16);
        #pragma unroll
        for (int nt = 0; nt < 2; ++nt)
            #pragma unroll
            for (int c = 0; c < 4; ++c) {
                float x = s[nt][c] * scale;
                if (maskt) {
                    const int col = kbase + wn * 16 + nt * 8 + tig * 2 + (c & 1);
                    const int row = q0 + wm * 16 + g + 8 * (c >> 1);
                    if (col > row) x = -1e30f;
                }
                s[nt][c] = x;
            }

        float mx0 = fmaxf(fmaxf(s[0][0], s[0][1]), fmaxf(s[1][0], s[1][1]));
        float mx1 = fmaxf(fmaxf(s[0][2], s[0][3]), fmaxf(s[1][2], s[1][3]));
        mx0 = fmaxf(mx0, __shfl_xor_sync(0xffffffffu, mx0, 1));
        mx0 = fmaxf(mx0, __shfl_xor_sync(0xffffffffu, mx0, 2));
        mx1 = fmaxf(mx1, __shfl_xor_sync(0xffffffffu, mx1, 1));
        mx1 = fmaxf(mx1, __shfl_xor_sync(0xffffffffu, mx1, 2));
        if (tig == 0) {
            redmx[wn * 64 + wm * 16 + g]     = mx0;
            redmx[wn * 64 + wm * 16 + g + 8] = mx1;
        }
        __syncthreads();

        const int r0 = wm * 16 + g, r1 = r0 + 8;
        const float mg0 = fmaxf(redmx[r0], redmx[64 + r0]);
        const float mg1 = fmaxf(redmx[r1], redmx[64 + r1]);
        const float mn0 = fmaxf(m_i[0], mg0);
        const float mn1 = fmaxf(m_i[1], mg1);
        const float cr0 = __expf(m_i[0] - mn0);
        const float cr1 = __expf(m_i[1] - mn1);

        float sum0 = 0.f, sum1 = 0.f;
        #pragma unroll
        for (int nt = 0; nt < 2; ++nt) {
            const int keyc = wn * 16 + nt * 8 + tig * 2;
            float p0 = __expf(s[nt][0] - mn0);
            float p1 = __expf(s[nt][1] - mn0);
            float p2 = __expf(s[nt][2] - mn1);
            float p3 = __expf(s[nt][3] - mn1);
            sum0 += p0 + p1; sum1 += p2 + p3;
            __nv_bfloat162 l0, l1;
            __nv_bfloat162 h0 = split_pair(p0, p1, &l0);
            __nv_bfloat162 h1 = split_pair(p2, p3, &l1);
            *(__nv_bfloat162*)(sm + SP_HI + r0 * PP + keyc * 2) = h0;
            *(__nv_bfloat162*)(sm + SP_LO + r0 * PP + keyc * 2) = l0;
            *(__nv_bfloat162*)(sm + SP_HI + r1 * PP + keyc * 2) = h1;
            *(__nv_bfloat162*)(sm + SP_LO + r1 * PP + keyc * 2) = l1;
        }
        sum0 += __shfl_xor_sync(0xffffffffu, sum0, 1);
        sum0 += __shfl_xor_sync(0xffffffffu, sum0, 2);
        sum1 += __shfl_xor_sync(0xffffffffu, sum1, 1);
        sum1 += __shfl_xor_sync(0xffffffffu, sum1, 2);
        if (tig == 0) {
            redsm[wn * 64 + r0] = sum0;
            redsm[wn * 64 + r1] = sum1;
        }
        __syncthreads();

        l_i[0] = l_i[0] * cr0 + redsm[r0] + redsm[64 + r0];
        l_i[1] = l_i[1] * cr1 + redsm[r1] + redsm[64 + r1];
        m_i[0] = mn0; m_i[1] = mn1;
        #pragma unroll
        for (int nt = 0; nt < 8; ++nt) {
            o[nt][0] *= cr0; o[nt][1] *= cr0;
            o[nt][2] *= cr1; o[nt][3] *= cr1;
        }

        #pragma unroll
        for (int ks = 0; ks < 2; ++ks) {
            const unsigned ko  = ks * 32;
            const unsigned kvo = ks * 16 * QP;
            unsigned ph[4], pl[4], vh[4][4], vl[4][4];
            ldm4(ph, smem + SP_HI + aP + ko);
            ldm4(pl, smem + SP_LO + aP + ko);
            #pragma unroll
            for (int p = 0; p < 4; ++p) {
                ldm4t(vh[p], smem + SV_HI + bVt + kvo + p * 32);
                ldm4t(vl[p], smem + SV_LO + bVt + kvo + p * 32);
            }
            #pragma unroll
            for (int nt = 0; nt < 8; ++nt)
                mma_bf16(o[nt], ph, &vh[nt >> 1][(nt & 1) * 2]);
            #pragma unroll
            for (int nt = 0; nt < 8; ++nt)
                mma_bf16(o[nt], ph, &vl[nt >> 1][(nt & 1) * 2]);
            #pragma unroll
            for (int nt = 0; nt < 8; ++nt)
                mma_bf16(o[nt], pl, &vh[nt >> 1][(nt & 1) * 2]);
        }
    }

    const float inv0 = 1.f / l_i[0];
    const float inv1 = 1.f / l_i[1];
    const int row0 = q0 + wm * 16 + g;
    #pragma unroll
    for (int nt = 0; nt < 8; ++nt) {
        const int col = wn * 64 + nt * 8 + tig * 2;
        const size_t i0 = headoff + (size_t)row0 * HID + col;
        const size_t i1 = headoff + (size_t)(row0 + 8) * HID + col;
        __nv_bfloat162 l0, l1;
        __nv_bfloat162 h0 = split_pair(o[nt][0] * inv0, o[nt][1] * inv0, &l0);
        __nv_bfloat162 h1 = split_pair(o[nt][2] * inv1, o[nt][3] * inv1, &l1);
        *(__nv_bfloat162*)(ohi + i0) = h0;
        *(__nv_bfloat162*)(olo + i0) = l0;
        *(__nv_bfloat162*)(ohi + i1) = h1;
        *(__nv_bfloat162*)(olo + i1) = l1;
    }
}

// ---------------------------------------------------------------------------
extern "C" void kernel_launch(void* const* d_in, const int* in_sizes, int n_in,
                              void* d_out, int out_size)
{
    (void)in_sizes; (void)n_in; (void)out_size;
    const float* x  = (const float*)d_in[0];
    const float* fr = (const float*)d_in[1];
    const float* w0 = (const float*)d_in[2];
    const float* w1 = (const float*)d_in[3];
    const float* w2 = (const float*)d_in[4];
    const float* w3 = (const float*)d_in[5];
    float* out = (float*)d_out;

    __nv_bfloat16 *xhi, *xlo, *whi, *wlo;
    __nv_bfloat16 *qhi, *qlo, *khi, *klo, *vhi, *vlo, *aohi, *aolo;
    cudaGetSymbolAddress((void**)&xhi,  g_x_hi);
    cudaGetSymbolAddress((void**)&xlo,  g_x_lo);
    cudaGetSymbolAddress((void**)&whi,  g_w_hi);
    cudaGetSymbolAddress((void**)&wlo,  g_w_lo);
    cudaGetSymbolAddress((void**)&qhi,  g_q_hi);
    cudaGetSymbolAddress((void**)&qlo,  g_q_lo);
    cudaGetSymbolAddress((void**)&khi,  g_k_hi);
    cudaGetSymbolAddress((void**)&klo,  g_k_lo);
    cudaGetSymbolAddress((void**)&vhi,  g_v_hi);
    cudaGetSymbolAddress((void**)&vlo,  g_v_lo);
    cudaGetSymbolAddress((void**)&aohi, g_ao_hi);
    cudaGetSymbolAddress((void**)&aolo, g_ao_lo);

    cudaFuncSetAttribute(gemm_qkv,    cudaFuncAttributeMaxDynamicSharedMemorySize, GEMM_SMEM);
    cudaFuncSetAttribute(gemm_single, cudaFuncAttributeMaxDynamicSharedMemorySize, GEMM_SMEM);
    cudaFuncSetAttribute(attn_mma,    cudaFuncAttributeMaxDynamicSharedMemorySize, ATTN_SMEM);

    split_all<<<(TOT4 + 255) / 256, 256>>>(x, w0, w1, w2, w3, xhi, xlo, whi, wlo);

    dim3 gqkv(HID / 128, MROWS / 128, 3);
    gemm_qkv<<<gqkv, 256, GEMM_SMEM>>>(xhi, xlo, whi, wlo,
                                       qhi, qlo, khi, klo, vhi, vlo, fr);

    attn_mma<<<dim3(SEQ / 64, BATCH * NHEAD), 256, ATTN_SMEM>>>(
        qhi, qlo, khi, klo, vhi, vlo, aohi, aolo);

    dim3 gg(HID / 128, MROWS / 128);
    gemm_single<<<gg, 256, GEMM_SMEM>>>(aohi, aolo, whi + 3 * (size_t)HID * HID,
                                        wlo + 3 * (size_t)HID * HID, out);
}